// round 1
// baseline (speedup 1.0000x reference)
#include <cuda_runtime.h>

// CrossLayer: out = DCN cross layers applied to x.
//   x:    (B, D)  B=16384, D=1024 fp32
//   W:    (L, D)  L=3
//   bias: (L, D)
// per row: cross = x; for l in 0..L-1: s = dot(cross, W[l]); cross = x*s + bias[l] + cross
//
// One 256-thread block per row. Each thread owns one float4 (4 elems) of the
// row in registers. W/bias read through __ldg (L1-resident, 24KB total).

#define D 1024
#define L 3
#define THREADS 256

__global__ __launch_bounds__(THREADS, 8)
void cross_layer_kernel(const float4* __restrict__ x4,
                        const float4* __restrict__ W4,
                        const float4* __restrict__ b4,
                        float4* __restrict__ out4)
{
    const int row = blockIdx.x;
    const int tid = threadIdx.x;
    const int lane = tid & 31;
    const int wid  = tid >> 5;

    __shared__ float red[8];
    __shared__ float ssum;

    const int base = row * (D / 4);
    float4 xv = x4[base + tid];
    float4 cr = xv;

    #pragma unroll
    for (int l = 0; l < L; l++) {
        const float4 w = __ldg(&W4[l * (D / 4) + tid]);

        // partial dot
        float p = cr.x * w.x + cr.y * w.y + cr.z * w.z + cr.w * w.w;

        // warp reduce
        #pragma unroll
        for (int o = 16; o > 0; o >>= 1)
            p += __shfl_xor_sync(0xFFFFFFFFu, p, o);

        if (lane == 0) red[wid] = p;
        __syncthreads();

        if (tid < 32) {
            float v = (tid < 8) ? red[tid] : 0.0f;
            #pragma unroll
            for (int o = 4; o > 0; o >>= 1)
                v += __shfl_xor_sync(0xFFFFFFFFu, v, o);
            if (tid == 0) ssum = v;
        }
        __syncthreads();

        const float s = ssum;
        const float4 b = __ldg(&b4[l * (D / 4) + tid]);

        cr.x = fmaf(xv.x, s, b.x + cr.x);
        cr.y = fmaf(xv.y, s, b.y + cr.y);
        cr.z = fmaf(xv.z, s, b.z + cr.z);
        cr.w = fmaf(xv.w, s, b.w + cr.w);

        // ssum/red are re-written only after the next iteration's first
        // __syncthreads(), so no extra barrier needed here.
        __syncthreads();
    }

    out4[base + tid] = cr;
}

extern "C" void kernel_launch(void* const* d_in, const int* in_sizes, int n_in,
                              void* d_out, int out_size)
{
    const float4* x4 = (const float4*)d_in[0];
    const float4* W4 = (const float4*)d_in[1];
    const float4* b4 = (const float4*)d_in[2];
    float4* out4 = (float4*)d_out;

    const int B = in_sizes[0] / D;   // 16384

    cross_layer_kernel<<<B, THREADS>>>(x4, W4, b4, out4);
}

// round 2
// speedup vs baseline: 1.0504x; 1.0504x over previous
#include <cuda_runtime.h>

// CrossLayer DCN: per row (D=1024 fp32), L=3 layers:
//   s = dot(cross, W[l]); cross = x*s + bias[l] + cross
//
// Block = 256 threads, thread owns float4 position tid.
// Each block processes G=8 rows; W/bias held in registers across rows
// (cuts W/bias L1 traffic 8x). Rows processed in pairs so the two
// reduction chains overlap and share barriers.

#define D 1024
#define L 3
#define THREADS 256
#define G 8

__global__ __launch_bounds__(THREADS)
void cross_layer_kernel(const float4* __restrict__ x4,
                        const float4* __restrict__ W4,
                        const float4* __restrict__ b4,
                        float4* __restrict__ out4)
{
    const int tid  = threadIdx.x;
    const int lane = tid & 31;
    const int wid  = tid >> 5;

    __shared__ float redA[8];
    __shared__ float redB[8];

    // W and bias resident in registers for all G rows.
    float4 w[L], b[L];
    #pragma unroll
    for (int l = 0; l < L; l++) {
        w[l] = __ldg(&W4[l * (D / 4) + tid]);
        b[l] = __ldg(&b4[l * (D / 4) + tid]);
    }

    const int row0 = blockIdx.x * G;

    #pragma unroll
    for (int g = 0; g < G; g += 2) {
        const int baseA = (row0 + g)     * (D / 4);
        const int baseB = (row0 + g + 1) * (D / 4);

        const float4 xA = x4[baseA + tid];
        const float4 xB = x4[baseB + tid];
        float4 cA = xA;
        float4 cB = xB;

        #pragma unroll
        for (int l = 0; l < L; l++) {
            // partial dots for both rows
            float pA = cA.x * w[l].x + cA.y * w[l].y + cA.z * w[l].z + cA.w * w[l].w;
            float pB = cB.x * w[l].x + cB.y * w[l].y + cB.z * w[l].z + cB.w * w[l].w;

            // interleaved warp reductions (independent chains overlap)
            #pragma unroll
            for (int o = 16; o > 0; o >>= 1) {
                pA += __shfl_xor_sync(0xFFFFFFFFu, pA, o);
                pB += __shfl_xor_sync(0xFFFFFFFFu, pB, o);
            }

            if (lane == 0) { redA[wid] = pA; redB[wid] = pB; }
            __syncthreads();

            // every thread sums the 8 warp partials itself (broadcast LDS,
            // conflict-free) — no second reduce stage, no extra broadcast.
            float sA = ((redA[0] + redA[1]) + (redA[2] + redA[3]))
                     + ((redA[4] + redA[5]) + (redA[6] + redA[7]));
            float sB = ((redB[0] + redB[1]) + (redB[2] + redB[3]))
                     + ((redB[4] + redB[5]) + (redB[6] + redB[7]));
            __syncthreads();   // reads done before next layer overwrites red*

            cA.x = fmaf(xA.x, sA, b[l].x + cA.x);
            cA.y = fmaf(xA.y, sA, b[l].y + cA.y);
            cA.z = fmaf(xA.z, sA, b[l].z + cA.z);
            cA.w = fmaf(xA.w, sA, b[l].w + cA.w);

            cB.x = fmaf(xB.x, sB, b[l].x + cB.x);
            cB.y = fmaf(xB.y, sB, b[l].y + cB.y);
            cB.z = fmaf(xB.z, sB, b[l].z + cB.z);
            cB.w = fmaf(xB.w, sB, b[l].w + cB.w);
        }

        out4[baseA + tid] = cA;
        out4[baseB + tid] = cB;
    }
}

extern "C" void kernel_launch(void* const* d_in, const int* in_sizes, int n_in,
                              void* d_out, int out_size)
{
    const float4* x4 = (const float4*)d_in[0];
    const float4* W4 = (const float4*)d_in[1];
    const float4* b4 = (const float4*)d_in[2];
    float4* out4 = (float4*)d_out;

    const int B = in_sizes[0] / D;   // 16384

    cross_layer_kernel<<<B / G, THREADS>>>(x4, W4, b4, out4);
}